// round 1
// baseline (speedup 1.0000x reference)
#include <cuda_runtime.h>
#include <cuda_bf16.h>
#include <cstddef>

// ---------------------------------------------------------------------------
// MultiHeadSelfAttention: B=2, S=2048, E=1024, H=16, D=64, fp32, causal.
// Pipeline:
//   1) sgemm_nt: QKV = X[4096,1024] @ Wqkv[3072,1024]^T  -> g_qkv[4096,3072]
//   2) attn:     flash-attention (causal, online softmax) -> g_e[4096,1024]
//   3) sgemm_nt: OUT = g_e @ W0[1024,1024]^T              -> d_out
// ---------------------------------------------------------------------------

#define S_LEN   2048
#define E_DIM   1024
#define N_HEAD  16
#define H_DIM   64

// scratch (device globals; no allocations allowed)
__device__ float g_qkv[2 * S_LEN * 3 * E_DIM];  // 12.6M floats
__device__ float g_e  [2 * S_LEN * E_DIM];      // 4.2M floats

// ---------------------------------------------------------------------------
// SGEMM: C[M,N] = A[M,K] * B[N,K]^T   (row-major, dims multiples of 128/16)
// 128x128 CTA tile, BK=16, 256 threads, 8x8 micro-tile.
// ---------------------------------------------------------------------------
#define GBM 128
#define GBN 128
#define GBK 16
#define GPAD 132   // smem row stride (floats) for A/B staging

__global__ __launch_bounds__(256, 2)
void sgemm_nt(const float* __restrict__ A, const float* __restrict__ B,
              float* __restrict__ C, int M, int N, int K) {
    __shared__ float As[GBK][GPAD];
    __shared__ float Bs[GBK][GPAD];

    const int tid = threadIdx.x;
    const int bm  = blockIdx.y * GBM;
    const int bn  = blockIdx.x * GBN;
    const int ty  = tid >> 4;          // 0..15 -> rows ty*8..ty*8+7
    const int tx  = tid & 15;          // 0..15 -> cols tx*8..tx*8+7

    const int lr = tid >> 2;           // 0..63
    const int lc = (tid & 3) * 4;      // 0,4,8,12

    float acc[8][8];
#pragma unroll
    for (int i = 0; i < 8; ++i)
#pragma unroll
        for (int j = 0; j < 8; ++j) acc[i][j] = 0.0f;

    for (int kk = 0; kk < K; kk += GBK) {
        float4 a0 = *(const float4*)(A + (size_t)(bm + lr)      * K + kk + lc);
        float4 a1 = *(const float4*)(A + (size_t)(bm + lr + 64) * K + kk + lc);
        float4 b0 = *(const float4*)(B + (size_t)(bn + lr)      * K + kk + lc);
        float4 b1 = *(const float4*)(B + (size_t)(bn + lr + 64) * K + kk + lc);

        __syncthreads();   // previous tile fully consumed
        As[lc + 0][lr] = a0.x; As[lc + 1][lr] = a0.y;
        As[lc + 2][lr] = a0.z; As[lc + 3][lr] = a0.w;
        As[lc + 0][lr + 64] = a1.x; As[lc + 1][lr + 64] = a1.y;
        As[lc + 2][lr + 64] = a1.z; As[lc + 3][lr + 64] = a1.w;
        Bs[lc + 0][lr] = b0.x; Bs[lc + 1][lr] = b0.y;
        Bs[lc + 2][lr] = b0.z; Bs[lc + 3][lr] = b0.w;
        Bs[lc + 0][lr + 64] = b1.x; Bs[lc + 1][lr + 64] = b1.y;
        Bs[lc + 2][lr + 64] = b1.z; Bs[lc + 3][lr + 64] = b1.w;
        __syncthreads();

#pragma unroll
        for (int k = 0; k < GBK; ++k) {
            float4 ra0 = *(const float4*)&As[k][ty * 8];
            float4 ra1 = *(const float4*)&As[k][ty * 8 + 4];
            float4 rb0 = *(const float4*)&Bs[k][tx * 8];
            float4 rb1 = *(const float4*)&Bs[k][tx * 8 + 4];
            float av[8] = {ra0.x, ra0.y, ra0.z, ra0.w, ra1.x, ra1.y, ra1.z, ra1.w};
            float bv[8] = {rb0.x, rb0.y, rb0.z, rb0.w, rb1.x, rb1.y, rb1.z, rb1.w};
#pragma unroll
            for (int i = 0; i < 8; ++i)
#pragma unroll
                for (int j = 0; j < 8; ++j)
                    acc[i][j] = fmaf(av[i], bv[j], acc[i][j]);
        }
    }

#pragma unroll
    for (int i = 0; i < 8; ++i) {
        float4 c0 = make_float4(acc[i][0], acc[i][1], acc[i][2], acc[i][3]);
        float4 c1 = make_float4(acc[i][4], acc[i][5], acc[i][6], acc[i][7]);
        float* crow = C + (size_t)(bm + ty * 8 + i) * N + bn + tx * 8;
        *(float4*)(crow)     = c0;
        *(float4*)(crow + 4) = c1;
    }
}

// ---------------------------------------------------------------------------
// Flash attention, fp32, causal. One CTA = one (batch, head, 64-row q-tile).
// BR=BC=64, D=64. 256 threads; 4x4 micro-tiles for both Q*K^T and P*V.
// Smem layouts (stride 68 floats to dodge bank conflicts):
//   Qs[d][r], Ks[d][c], Vs[c][d], Ps[c][r]
// ---------------------------------------------------------------------------
#define SSTR 68
#define ATTN_SMEM (4 * 64 * SSTR * 4)   // bytes = 69632

__global__ __launch_bounds__(256)
void attn_kernel(const float* __restrict__ qkv, float* __restrict__ e) {
    extern __shared__ float sm[];
    float* Qs = sm;                 // [64][SSTR]  (d-major)
    float* Ks = sm + 64 * SSTR;     // [64][SSTR]  (d-major)
    float* Vs = sm + 2 * 64 * SSTR; // [64][SSTR]  (c-major)
    float* Ps = sm + 3 * 64 * SSTR; // [64][SSTR]  (c-major)

    const int tid = threadIdx.x;
    const int q0  = blockIdx.x * 64;
    const int h   = blockIdx.y;
    const int b   = blockIdx.z;
    const int ty  = tid >> 4;   // 0..15 -> rows ty*4..+3
    const int tx  = tid & 15;   // 0..15 -> cols tx*4..+3

    const size_t base = (size_t)(b * S_LEN) * (3 * E_DIM) + h * H_DIM;

    // load Q tile transposed: Qs[d][r]
#pragma unroll
    for (int it = 0; it < 4; ++it) {
        int i  = tid + it * 256;
        int r  = i >> 4;
        int c4 = (i & 15) * 4;
        float4 v = *(const float4*)(qkv + base + (size_t)(q0 + r) * (3 * E_DIM) + c4);
        Qs[(c4 + 0) * SSTR + r] = v.x;
        Qs[(c4 + 1) * SSTR + r] = v.y;
        Qs[(c4 + 2) * SSTR + r] = v.z;
        Qs[(c4 + 3) * SSTR + r] = v.w;
    }

    float m_i[4], l_i[4], o[4][4];
#pragma unroll
    for (int i = 0; i < 4; ++i) {
        m_i[i] = -1e30f; l_i[i] = 0.0f;
#pragma unroll
        for (int j = 0; j < 4; ++j) o[i][j] = 0.0f;
    }

    const int ntiles = blockIdx.x + 1;   // causal: k-tiles 0..q0/64
    const float scale = 0.125f;          // 1/sqrt(64)

    for (int t = 0; t < ntiles; ++t) {
        const int k0 = t * 64;
        __syncthreads();   // previous PV consumed Ks/Vs/Ps

        // load K transposed Ks[d][c], V natural Vs[c][d]
#pragma unroll
        for (int it = 0; it < 4; ++it) {
            int i  = tid + it * 256;
            int r  = i >> 4;
            int c4 = (i & 15) * 4;
            const float* gk = qkv + base + E_DIM     + (size_t)(k0 + r) * (3 * E_DIM) + c4;
            const float* gv = qkv + base + 2 * E_DIM + (size_t)(k0 + r) * (3 * E_DIM) + c4;
            float4 kv = *(const float4*)gk;
            Ks[(c4 + 0) * SSTR + r] = kv.x;
            Ks[(c4 + 1) * SSTR + r] = kv.y;
            Ks[(c4 + 2) * SSTR + r] = kv.z;
            Ks[(c4 + 3) * SSTR + r] = kv.w;
            *(float4*)(Vs + r * SSTR + c4) = *(const float4*)gv;
        }
        __syncthreads();

        // S = Q * K^T  (4x4 micro)
        float s[4][4];
#pragma unroll
        for (int i = 0; i < 4; ++i)
#pragma unroll
            for (int j = 0; j < 4; ++j) s[i][j] = 0.0f;

#pragma unroll 8
        for (int d = 0; d < 64; ++d) {
            float4 qa = *(const float4*)(Qs + d * SSTR + ty * 4);
            float4 kb = *(const float4*)(Ks + d * SSTR + tx * 4);
            float av[4] = {qa.x, qa.y, qa.z, qa.w};
            float bv[4] = {kb.x, kb.y, kb.z, kb.w};
#pragma unroll
            for (int i = 0; i < 4; ++i)
#pragma unroll
                for (int j = 0; j < 4; ++j)
                    s[i][j] = fmaf(av[i], bv[j], s[i][j]);
        }

        // scale + causal mask (diagonal tile: k0 == q0 -> mask c > r)
        const bool diag = (t == ntiles - 1);
#pragma unroll
        for (int i = 0; i < 4; ++i)
#pragma unroll
            for (int j = 0; j < 4; ++j) {
                if (diag && (tx * 4 + j > ty * 4 + i)) s[i][j] = -1e30f;
                else                                   s[i][j] *= scale;
            }

        // online softmax: row max across 16 threads (width-16 butterfly)
        float rmax[4];
#pragma unroll
        for (int i = 0; i < 4; ++i) {
            rmax[i] = fmaxf(fmaxf(s[i][0], s[i][1]), fmaxf(s[i][2], s[i][3]));
#pragma unroll
            for (int off = 8; off >= 1; off >>= 1)
                rmax[i] = fmaxf(rmax[i], __shfl_xor_sync(0xffffffffu, rmax[i], off));
        }

        float alpha[4];
#pragma unroll
        for (int i = 0; i < 4; ++i) {
            float mnew = fmaxf(m_i[i], rmax[i]);
            alpha[i] = __expf(m_i[i] - mnew);
            m_i[i] = mnew;
        }

        float rsum[4];
#pragma unroll
        for (int i = 0; i < 4; ++i) {
#pragma unroll
            for (int j = 0; j < 4; ++j) s[i][j] = __expf(s[i][j] - m_i[i]);
            rsum[i] = (s[i][0] + s[i][1]) + (s[i][2] + s[i][3]);
#pragma unroll
            for (int off = 8; off >= 1; off >>= 1)
                rsum[i] += __shfl_xor_sync(0xffffffffu, rsum[i], off);
            l_i[i] = l_i[i] * alpha[i] + rsum[i];
#pragma unroll
            for (int j = 0; j < 4; ++j) o[i][j] *= alpha[i];
        }

        // write P transposed: Ps[c][r]
#pragma unroll
        for (int i = 0; i < 4; ++i)
#pragma unroll
            for (int j = 0; j < 4; ++j)
                Ps[(tx * 4 + j) * SSTR + (ty * 4 + i)] = s[i][j];
        __syncthreads();

        // O += P * V  (4x4 micro over d-cols tx*4..+3)
#pragma unroll 8
        for (int c = 0; c < 64; ++c) {
            float4 pa = *(const float4*)(Ps + c * SSTR + ty * 4);
            float4 vb = *(const float4*)(Vs + c * SSTR + tx * 4);
            float av[4] = {pa.x, pa.y, pa.z, pa.w};
            float bv[4] = {vb.x, vb.y, vb.z, vb.w};
#pragma unroll
            for (int i = 0; i < 4; ++i)
#pragma unroll
                for (int j = 0; j < 4; ++j)
                    o[i][j] = fmaf(av[i], bv[j], o[i][j]);
        }
    }

    // epilogue: normalize and store to merged-head layout e[b, s, h*64+d]
#pragma unroll
    for (int i = 0; i < 4; ++i) {
        float inv = 1.0f / l_i[i];
        float4 ov = make_float4(o[i][0] * inv, o[i][1] * inv,
                                o[i][2] * inv, o[i][3] * inv);
        size_t row = (size_t)(b * S_LEN + q0 + ty * 4 + i);
        *(float4*)(e + row * E_DIM + h * H_DIM + tx * 4) = ov;
    }
}

// ---------------------------------------------------------------------------
// launch
// ---------------------------------------------------------------------------
extern "C" void kernel_launch(void* const* d_in, const int* in_sizes, int n_in,
                              void* d_out, int out_size) {
    (void)in_sizes; (void)n_in; (void)out_size;
    const float* x    = (const float*)d_in[0];   // [2,2048,1024]
    const float* wqkv = (const float*)d_in[1];   // [3072,1024]
    const float* w0   = (const float*)d_in[2];   // [1024,1024]
    float* out = (float*)d_out;                  // [2,2048,1024]

    float *qkv_ptr = nullptr, *e_ptr = nullptr;
    cudaGetSymbolAddress((void**)&qkv_ptr, g_qkv);
    cudaGetSymbolAddress((void**)&e_ptr,   g_e);

    cudaFuncSetAttribute(attn_kernel,
                         cudaFuncAttributeMaxDynamicSharedMemorySize, ATTN_SMEM);

    const int M = 2 * S_LEN;  // 4096

    // 1) QKV projection: [4096,3072] = X @ Wqkv^T
    sgemm_nt<<<dim3(3 * E_DIM / GBN, M / GBM), 256>>>(x, wqkv, qkv_ptr, M, 3 * E_DIM, E_DIM);

    // 2) causal flash attention
    attn_kernel<<<dim3(S_LEN / 64, N_HEAD, 2), 256, ATTN_SMEM>>>(qkv_ptr, e_ptr);

    // 3) output projection: [4096,1024] = E @ W0^T
    sgemm_nt<<<dim3(E_DIM / GBN, M / GBM), 256>>>(e_ptr, w0, out, M, E_DIM, E_DIM);
}

// round 3
// speedup vs baseline: 1.1416x; 1.1416x over previous
#include <cuda_runtime.h>
#include <cuda_bf16.h>
#include <cstdint>
#include <cstddef>

// ---------------------------------------------------------------------------
// MultiHeadSelfAttention: B=2, S=2048, E=1024, H=16, D=64, fp32, causal.
// All matmuls on tensor cores via mma.sync.m16n8k16 bf16 (plain sm_103 PTX),
// with split-bf16 (hi+lo, 3-term products) for fp32-grade accuracy (~1e-5).
//   1) split3: X, Wqkv -> bf16 [hi|lo|hi] / [hi|hi|lo], K'=3072
//   2) gemm_bf16_mma: QKV = X' @ Wqkv'^T (fp32 accum)
//   3) attn_mma: causal flash attention, mma.sync, split-bf16 QK / PV
//   4) split3: E, W0 ; 5) gemm_bf16_mma: OUT = E' @ W0'^T
// ---------------------------------------------------------------------------

#define S_LEN   2048
#define E_DIM   1024
#define N_HEAD  16
#define H_DIM   64
#define K3      3072

__device__ float g_qkv[2 * S_LEN * 3 * E_DIM];
__device__ float g_e  [2 * S_LEN * E_DIM];
__device__ __nv_bfloat16 g_a2[4096 * K3];
__device__ __nv_bfloat16 g_w2[3072 * K3];

// ---------------------------------------------------------------------------
// helpers
// ---------------------------------------------------------------------------
__device__ __forceinline__ uint32_t smem_u32(const void* p) {
    uint32_t a;
    asm("{ .reg .u64 t; cvta.to.shared.u64 t, %1; cvt.u32.u64 %0, t; }"
        : "=r"(a) : "l"(p));
    return a;
}
__device__ __forceinline__ uint32_t pk(__nv_bfloat16 a, __nv_bfloat16 b) {
    __nv_bfloat162 t = __halves2bfloat162(a, b);
    return *reinterpret_cast<uint32_t*>(&t);
}
__device__ __forceinline__ void ldsm4(uint32_t r[4], uint32_t addr) {
    asm volatile("ldmatrix.sync.aligned.m8n8.x4.shared.b16 {%0,%1,%2,%3}, [%4];"
                 : "=r"(r[0]), "=r"(r[1]), "=r"(r[2]), "=r"(r[3]) : "r"(addr));
}
__device__ __forceinline__ void mma16816(float c[4], const uint32_t a[4],
                                         uint32_t b0, uint32_t b1) {
    asm volatile("mma.sync.aligned.m16n8k16.row.col.f32.bf16.bf16.f32 "
                 "{%0,%1,%2,%3}, {%4,%5,%6,%7}, {%8,%9}, {%0,%1,%2,%3};"
                 : "+f"(c[0]), "+f"(c[1]), "+f"(c[2]), "+f"(c[3])
                 : "r"(a[0]), "r"(a[1]), "r"(a[2]), "r"(a[3]), "r"(b0), "r"(b1));
}
__device__ __forceinline__ void cpa16(uint32_t dst, const void* src) {
    asm volatile("cp.async.cg.shared.global [%0], [%1], 16;" :: "r"(dst), "l"(src));
}

// ---------------------------------------------------------------------------
// split3: fp32 [rows,K] -> bf16 [rows,3K]. loblk==1: [hi|lo|hi]; 2: [hi|hi|lo]
// ---------------------------------------------------------------------------
__global__ void split3_kernel(const float* __restrict__ src,
                              __nv_bfloat16* __restrict__ dst,
                              int rows, int K, int loblk) {
    int t = blockIdx.x * blockDim.x + threadIdx.x;
    int per4 = K >> 2;
    if (t >= rows * per4) return;
    int r = t / per4, c4 = (t - r * per4) * 4;
    float4 v = ((const float4*)src)[t];

    __nv_bfloat16 h0 = __float2bfloat16(v.x), h1 = __float2bfloat16(v.y);
    __nv_bfloat16 h2 = __float2bfloat16(v.z), h3 = __float2bfloat16(v.w);
    __nv_bfloat16 l0 = __float2bfloat16(v.x - __bfloat162float(h0));
    __nv_bfloat16 l1 = __float2bfloat16(v.y - __bfloat162float(h1));
    __nv_bfloat16 l2 = __float2bfloat16(v.z - __bfloat162float(h2));
    __nv_bfloat16 l3 = __float2bfloat16(v.w - __bfloat162float(h3));

    uint2 hp = make_uint2(pk(h0, h1), pk(h2, h3));
    uint2 lp = make_uint2(pk(l0, l1), pk(l2, l3));

    __nv_bfloat16* d0 = dst + (size_t)r * (3 * K) + c4;
    *(uint2*)(d0)         = hp;
    *(uint2*)(d0 + K)     = (loblk == 1) ? lp : hp;
    *(uint2*)(d0 + 2 * K) = (loblk == 1) ? hp : lp;
}

// ---------------------------------------------------------------------------
// GEMM: C[M,N] = A[M,K] @ B[N,K]^T, bf16 in / fp32 out, mma.sync.
// 128x128 CTA tile, BK=32, 256 threads (8 warps = 2m x 4n), 2-stage cp.async.
// smem row stride 40 bf16 (80B = 5x16B, odd -> ldmatrix conflict-free).
// ---------------------------------------------------------------------------
#define GBM 128
#define GBN 128
#define GBK 32
#define GSTR 40
#define GA_BF (GBM * GSTR)
#define GB_BF (GBN * GSTR)
#define GSTAGE_BF (GA_BF + GB_BF)
#define GEMM_SMEM (2 * GSTAGE_BF * 2)   // 40960 B

__global__ __launch_bounds__(256)
void gemm_bf16_mma(const __nv_bfloat16* __restrict__ A,
                   const __nv_bfloat16* __restrict__ B,
                   float* __restrict__ C, int M, int N, int K) {
    extern __shared__ __nv_bfloat16 sh[];
    const uint32_t sb = smem_u32(sh);
    const int tid = threadIdx.x, wid = tid >> 5, lane = tid & 31;
    const int bm = blockIdx.y * GBM, bn = blockIdx.x * GBN;
    const int wm = (wid >> 2) * 64, wn = (wid & 3) * 32;
    const int g = lane >> 2, tg = lane & 3;

    auto load_stage = [&](int s, int kk) {
        uint32_t abase = sb + (uint32_t)s * GSTAGE_BF * 2;
        uint32_t bbase = abase + GA_BF * 2;
#pragma unroll
        for (int i = 0; i < 2; ++i) {
            int c = tid + i * 256;               // 512 16B chunks for A
            int row = c >> 2, k16 = c & 3;
            cpa16(abase + row * 80 + k16 * 16,
                  A + (size_t)(bm + row) * K + kk + k16 * 8);
        }
#pragma unroll
        for (int i = 0; i < 2; ++i) {
            int c = tid + i * 256;               // 512 for B
            int row = c >> 2, k16 = c & 3;
            cpa16(bbase + row * 80 + k16 * 16,
                  B + (size_t)(bn + row) * K + kk + k16 * 8);
        }
        asm volatile("cp.async.commit_group;" ::: "memory");
    };

    float acc[4][4][4];
#pragma unroll
    for (int i = 0; i < 4; ++i)
#pragma unroll
        for (int j = 0; j < 4; ++j)
#pragma unroll
            for (int e = 0; e < 4; ++e) acc[i][j][e] = 0.0f;

    const int NC = K / GBK;   // 96
    load_stage(0, 0);
    load_stage(1, GBK);

    for (int c = 0; c < NC; ++c) {
        const int st = c & 1;
        if (c + 1 < NC) asm volatile("cp.async.wait_group 1;" ::: "memory");
        else            asm volatile("cp.async.wait_group 0;" ::: "memory");
        __syncthreads();

        uint32_t abase = sb + (uint32_t)st * GSTAGE_BF * 2;
        uint32_t bbase = abase + GA_BF * 2;
        const int lrow = lane & 15, lcol = (lane >> 4) * 8;

#pragma unroll
        for (int ks = 0; ks < 2; ++ks) {
            uint32_t a[4][4];
#pragma unroll
            for (int mt = 0; mt < 4; ++mt)
                ldsm4(a[mt], abase + ((wm + mt * 16 + lrow) * GSTR + ks * 16 + lcol) * 2);
            uint32_t bf[4][2];
#pragma unroll
            for (int nb = 0; nb < 2; ++nb) {
                uint32_t r[4];
                ldsm4(r, bbase + ((wn + nb * 16 + lrow) * GSTR + ks * 16 + lcol) * 2);
                bf[nb * 2][0] = r[0];     bf[nb * 2][1] = r[2];
                bf[nb * 2 + 1][0] = r[1]; bf[nb * 2 + 1][1] = r[3];
            }
#pragma unroll
            for (int mt = 0; mt < 4; ++mt)
#pragma unroll
                for (int nt = 0; nt < 4; ++nt)
                    mma16816(acc[mt][nt], a[mt], bf[nt][0], bf[nt][1]);
        }
        __syncthreads();
        if (c + 2 < NC) load_stage(st, (c + 2) * GBK);
    }

    // epilogue
#pragma unroll
    for (int mt = 0; mt < 4; ++mt) {
        int r0 = bm + wm + mt * 16 + g;
#pragma unroll
        for (int nt = 0; nt < 4; ++nt) {
            int col = bn + wn + nt * 8 + tg * 2;
            *(float2*)(C + (size_t)r0 * N + col) =
                make_float2(acc[mt][nt][0], acc[mt][nt][1]);
            *(float2*)(C + (size_t)(r0 + 8) * N + col) =
                make_float2(acc[mt][nt][2], acc[mt][nt][3]);
        }
    }
}

// ---------------------------------------------------------------------------
// Flash attention with mma.sync, causal. 128 threads (4 warps), BR=BC=64.
// Q/K split-bf16 concat over d (K'=192): Qs=[hi|lo|hi], Ks=[hi|hi|lo].
// V split planes Vt[d][c_hi(0-63) | c_lo(64-127)]; P split in registers.
// Warp w owns q-rows w*16..+15. S fragment reused directly as A fragment.
// ---------------------------------------------------------------------------
#define QS 200   // 400B = 25x16B (odd) -> conflict-free ldmatrix
#define VS 136   // 272B = 17x16B (odd)
#define ATT_SMEM ((2 * 64 * QS + 64 * VS) * 2)   // 68608 B

__global__ __launch_bounds__(128)
void attn_mma(const float* __restrict__ qkv, float* __restrict__ e) {
    extern __shared__ __nv_bfloat16 sh[];
    __nv_bfloat16* Qs = sh;
    __nv_bfloat16* Ks = sh + 64 * QS;
    __nv_bfloat16* Vt = sh + 2 * 64 * QS;
    const uint32_t sbQ = smem_u32(Qs), sbK = smem_u32(Ks), sbV = smem_u32(Vt);

    const int tid = threadIdx.x, wid = tid >> 5, lane = tid & 31;
    const int q0 = blockIdx.x * 64, h = blockIdx.y, b = blockIdx.z;
    const int g = lane >> 2, tg = lane & 3;
    const size_t base = (size_t)(b * S_LEN) * K3 + h * H_DIM;

    // ---- load Q tile, split to [hi|lo|hi]
#pragma unroll
    for (int i = 0; i < 8; ++i) {
        int fid = tid + i * 128;
        int row = fid >> 4, c4 = (fid & 15) * 4;
        float4 v = *(const float4*)(qkv + base + (size_t)(q0 + row) * K3 + c4);
        __nv_bfloat16 h0 = __float2bfloat16(v.x), h1 = __float2bfloat16(v.y);
        __nv_bfloat16 h2 = __float2bfloat16(v.z), h3 = __float2bfloat16(v.w);
        uint32_t p01 = pk(h0, h1), p23 = pk(h2, h3);
        uint32_t l01 = pk(__float2bfloat16(v.x - __bfloat162float(h0)),
                          __float2bfloat16(v.y - __bfloat162float(h1)));
        uint32_t l23 = pk(__float2bfloat16(v.z - __bfloat162float(h2)),
                          __float2bfloat16(v.w - __bfloat162float(h3)));
        __nv_bfloat16* qr = Qs + row * QS;
        *(uint32_t*)(qr + c4) = p01;       *(uint32_t*)(qr + c4 + 2) = p23;
        *(uint32_t*)(qr + 64 + c4) = l01;  *(uint32_t*)(qr + 64 + c4 + 2) = l23;
        *(uint32_t*)(qr + 128 + c4) = p01; *(uint32_t*)(qr + 128 + c4 + 2) = p23;
    }

    float m0 = -1e30f, m1 = -1e30f, l0 = 0.0f, l1 = 0.0f;
    float o[8][4];
#pragma unroll
    for (int i = 0; i < 8; ++i)
#pragma unroll
        for (int j = 0; j < 4; ++j) o[i][j] = 0.0f;

    const int qt = blockIdx.x;
    const int lrow = lane & 15, lcol = (lane >> 4) * 8;
    const int rowg0 = q0 + wid * 16 + g, rowg1 = rowg0 + 8;

    for (int t = 0; t <= qt; ++t) {
        const int k0 = t * 64;
        __syncthreads();   // previous tile fully consumed (and Q ready on t=0)

        // ---- load K tile -> [hi|hi|lo]; V tile -> transposed hi/lo planes
#pragma unroll
        for (int i = 0; i < 8; ++i) {
            int fid = tid + i * 128;
            int row = fid >> 4, c4 = (fid & 15) * 4;
            float4 kv = *(const float4*)(qkv + base + E_DIM +
                                         (size_t)(k0 + row) * K3 + c4);
            __nv_bfloat16 h0 = __float2bfloat16(kv.x), h1 = __float2bfloat16(kv.y);
            __nv_bfloat16 h2 = __float2bfloat16(kv.z), h3 = __float2bfloat16(kv.w);
            uint32_t p01 = pk(h0, h1), p23 = pk(h2, h3);
            uint32_t l01 = pk(__float2bfloat16(kv.x - __bfloat162float(h0)),
                              __float2bfloat16(kv.y - __bfloat162float(h1)));
            uint32_t l23 = pk(__float2bfloat16(kv.z - __bfloat162float(h2)),
                              __float2bfloat16(kv.w - __bfloat162float(h3)));
            __nv_bfloat16* kr = Ks + row * QS;
            *(uint32_t*)(kr + c4) = p01;        *(uint32_t*)(kr + c4 + 2) = p23;
            *(uint32_t*)(kr + 64 + c4) = p01;   *(uint32_t*)(kr + 64 + c4 + 2) = p23;
            *(uint32_t*)(kr + 128 + c4) = l01;  *(uint32_t*)(kr + 128 + c4 + 2) = l23;

            float4 vv = *(const float4*)(qkv + base + 2 * E_DIM +
                                         (size_t)(k0 + row) * K3 + c4);
            float vf[4] = {vv.x, vv.y, vv.z, vv.w};
#pragma unroll
            for (int j = 0; j < 4; ++j) {
                __nv_bfloat16 vh = __float2bfloat16(vf[j]);
                Vt[(c4 + j) * VS + row]      = vh;
                Vt[(c4 + j) * VS + 64 + row] =
                    __float2bfloat16(vf[j] - __bfloat162float(vh));
            }
        }
        __syncthreads();

        // ---- S = Q K^T over K'=192
        float s[8][4];
#pragma unroll
        for (int i = 0; i < 8; ++i)
#pragma unroll
            for (int j = 0; j < 4; ++j) s[i][j] = 0.0f;

#pragma unroll
        for (int ks = 0; ks < 12; ++ks) {
            uint32_t qa[4];
            ldsm4(qa, sbQ + ((wid * 16 + lrow) * QS + ks * 16 + lcol) * 2);
#pragma unroll
            for (int nb = 0; nb < 4; ++nb) {
                uint32_t r[4];
                ldsm4(r, sbK + ((nb * 16 + lrow) * QS + ks * 16 + lcol) * 2);
                mma16816(s[nb * 2],     qa, r[0], r[2]);
                mma16816(s[nb * 2 + 1], qa, r[1], r[3]);
            }
        }

        // ---- scale + causal mask
        const bool diag = (t == qt);
#pragma unroll
        for (int nt = 0; nt < 8; ++nt)
#pragma unroll
            for (int ee = 0; ee < 4; ++ee) {
                int col = k0 + nt * 8 + tg * 2 + (ee & 1);
                int row = (ee < 2) ? rowg0 : rowg1;
                if (diag && col > row) s[nt][ee] = -1e30f;
                else                   s[nt][ee] *= 0.125f;
            }

        // ---- online softmax (rows distributed over quad lanes)
        float rmax0 = -1e30f, rmax1 = -1e30f;
#pragma unroll
        for (int nt = 0; nt < 8; ++nt) {
            rmax0 = fmaxf(rmax0, fmaxf(s[nt][0], s[nt][1]));
            rmax1 = fmaxf(rmax1, fmaxf(s[nt][2], s[nt][3]));
        }
        rmax0 = fmaxf(rmax0, __shfl_xor_sync(0xffffffffu, rmax0, 1));
        rmax0 = fmaxf(rmax0, __shfl_xor_sync(0xffffffffu, rmax0, 2));
        rmax1 = fmaxf(rmax1, __shfl_xor_sync(0xffffffffu, rmax1, 1));
        rmax1 = fmaxf(rmax1, __shfl_xor_sync(0xffffffffu, rmax1, 2));

        float mn0 = fmaxf(m0, rmax0), mn1 = fmaxf(m1, rmax1);
        float al0 = __expf(m0 - mn0), al1 = __expf(m1 - mn1);
        m0 = mn0; m1 = mn1;

        float rs0 = 0.0f, rs1 = 0.0f;
#pragma unroll
        for (int nt = 0; nt < 8; ++nt) {
            s[nt][0] = __expf(s[nt][0] - m0);
            s[nt][1] = __expf(s[nt][1] - m0);
            s[nt][2] = __expf(s[nt][2] - m1);
            s[nt][3] = __expf(s[nt][3] - m1);
            rs0 += s[nt][0] + s[nt][1];
            rs1 += s[nt][2] + s[nt][3];
        }
        rs0 += __shfl_xor_sync(0xffffffffu, rs0, 1);
        rs0 += __shfl_xor_sync(0xffffffffu, rs0, 2);
        rs1 += __shfl_xor_sync(0xffffffffu, rs1, 1);
        rs1 += __shfl_xor_sync(0xffffffffu, rs1, 2);
        l0 = l0 * al0 + rs0;
        l1 = l1 * al1 + rs1;
#pragma unroll
        for (int nt = 0; nt < 8; ++nt) {
            o[nt][0] *= al0; o[nt][1] *= al0;
            o[nt][2] *= al1; o[nt][3] *= al1;
        }

        // ---- P -> bf16 A-fragments (hi & lo), directly from S fragments
        uint32_t ph[4][4], pl[4][4];
#pragma unroll
        for (int kc = 0; kc < 4; ++kc) {
            const float* se = s[kc * 2];
            const float* so = s[kc * 2 + 1];
            __nv_bfloat16 he0 = __float2bfloat16(se[0]), he1 = __float2bfloat16(se[1]);
            __nv_bfloat16 he2 = __float2bfloat16(se[2]), he3 = __float2bfloat16(se[3]);
            __nv_bfloat16 ho0 = __float2bfloat16(so[0]), ho1 = __float2bfloat16(so[1]);
            __nv_bfloat16 ho2 = __float2bfloat16(so[2]), ho3 = __float2bfloat16(so[3]);
            ph[kc][0] = pk(he0, he1);
            ph[kc][1] = pk(he2, he3);
            ph[kc][2] = pk(ho0, ho1);
            ph[kc][3] = pk(ho2, ho3);
            pl[kc][0] = pk(__float2bfloat16(se[0] - __bfloat162float(he0)),
                           __float2bfloat16(se[1] - __bfloat162float(he1)));
            pl[kc][1] = pk(__float2bfloat16(se[2] - __bfloat162float(he2)),
                           __float2bfloat16(se[3] - __bfloat162float(he3)));
            pl[kc][2] = pk(__float2bfloat16(so[0] - __bfloat162float(ho0)),
                           __float2bfloat16(so[1] - __bfloat162float(ho1)));
            pl[kc][3] = pk(__float2bfloat16(so[2] - __bfloat162float(ho2)),
                           __float2bfloat16(so[3] - __bfloat162float(ho3)));
        }

        // ---- O += Ph*Vh + Pl*Vh + Ph*Vl
#pragma unroll
        for (int kc = 0; kc < 4; ++kc) {
#pragma unroll
            for (int db = 0; db < 4; ++db) {
                uint32_t r[4];
                ldsm4(r, sbV + ((db * 16 + lrow) * VS + kc * 16 + lcol) * 2);
                mma16816(o[db * 2],     ph[kc], r[0], r[2]);
                mma16816(o[db * 2 + 1], ph[kc], r[1], r[3]);
                mma16816(o[db * 2],     pl[kc], r[0], r[2]);
                mma16816(o[db * 2 + 1], pl[kc], r[1], r[3]);
                uint32_t rl[4];
                ldsm4(rl, sbV + ((db * 16 + lrow) * VS + 64 + kc * 16 + lcol) * 2);
                mma16816(o[db * 2],     ph[kc], rl[0], rl[2]);
                mma16816(o[db * 2 + 1], ph[kc], rl[1], rl[3]);
            }
        }
    }

    // ---- epilogue
    float inv0 = 1.0f / l0, inv1 = 1.0f / l1;
    size_t r0 = (size_t)(b * S_LEN) + rowg0;
    size_t r1 = (size_t)(b * S_LEN) + rowg1;
#pragma unroll
    for (int nt = 0; nt < 8; ++nt) {
        int col = h * H_DIM + nt * 8 + tg * 2;
        *(float2*)(e + r0 * E_DIM + col) = make_float2(o[nt][0] * inv0, o[nt][1] * inv0);
        *(float2*)(e + r1 * E_DIM + col) = make_float2(o[nt][2] * inv1, o[nt][3] * inv1);
    }
}

// ---------------------------------------------------------------------------
// launch
// ---------------------------------------------------------------------------
extern "C" void kernel_launch(void* const* d_in, const int* in_sizes, int n_in,
                              void* d_out, int out_size) {
    (void)in_sizes; (void)n_in; (void)out_size;
    const float* x    = (const float*)d_in[0];
    const float* wqkv = (const float*)d_in[1];
    const float* w0   = (const float*)d_in[2];
    float* out = (float*)d_out;

    float *qkv_ptr = nullptr, *e_ptr = nullptr;
    __nv_bfloat16 *a2 = nullptr, *w2 = nullptr;
    cudaGetSymbolAddress((void**)&qkv_ptr, g_qkv);
    cudaGetSymbolAddress((void**)&e_ptr,   g_e);
    cudaGetSymbolAddress((void**)&a2,      g_a2);
    cudaGetSymbolAddress((void**)&w2,      g_w2);

    cudaFuncSetAttribute(gemm_bf16_mma,
                         cudaFuncAttributeMaxDynamicSharedMemorySize, GEMM_SMEM);
    cudaFuncSetAttribute(attn_mma,
                         cudaFuncAttributeMaxDynamicSharedMemorySize, ATT_SMEM);

    const int M = 2 * S_LEN;  // 4096

    split3_kernel<<<(M * E_DIM / 4 + 255) / 256, 256>>>(x, a2, M, E_DIM, 1);
    split3_kernel<<<(3 * E_DIM * E_DIM / 4 + 255) / 256, 256>>>(wqkv, w2, 3 * E_DIM, E_DIM, 2);

    gemm_bf16_mma<<<dim3(3 * E_DIM / GBN, M / GBM), 256, GEMM_SMEM>>>(
        a2, w2, qkv_ptr, M, 3 * E_DIM, K3);

    attn_mma<<<dim3(S_LEN / 64, N_HEAD, 2), 128, ATT_SMEM>>>(qkv_ptr, e_ptr);

    split3_kernel<<<(M * E_DIM / 4 + 255) / 256, 256>>>(e_ptr, a2, M, E_DIM, 1);
    split3_kernel<<<(E_DIM * E_DIM / 4 + 255) / 256, 256>>>(w0, w2, E_DIM, E_DIM, 2);

    gemm_bf16_mma<<<dim3(E_DIM / GBN, M / GBM), 256, GEMM_SMEM>>>(
        a2, w2, out, M, E_DIM, K3);
}

// round 5
// speedup vs baseline: 2.3316x; 2.0423x over previous
#include <cuda_runtime.h>
#include <cuda_bf16.h>
#include <cstdint>
#include <cstddef>

// ---------------------------------------------------------------------------
// MHA: B=2, S=2048, E=1024, H=16, D=64, fp32, causal. mma.sync bf16 split-hi/lo.
//  split3(x)->A', split3(wqkv)->B'
//  gemm1 (fused epi): Q'[hi|lo|hi], K'[hi|hi|lo] (192), V'[hi|lo] (128) bf16
//  attn (BR=128, preconverted, ldmatrix.trans V) -> E' split [hi|lo|hi]
//  split3(w0)->B' ; gemm2 -> fp32 out
// ---------------------------------------------------------------------------

#define S_LEN   2048
#define E_DIM   1024
#define K3      3072

__device__ __nv_bfloat16 g_a2[4096 * K3];            // X' then E'
__device__ __nv_bfloat16 g_w2[3072 * K3];            // Wqkv' then W0'
__device__ __nv_bfloat16 g_q [32 * 2048 * 192];      // Q' per (b,h)
__device__ __nv_bfloat16 g_k [32 * 2048 * 192];      // K'
__device__ __nv_bfloat16 g_v [32 * 2048 * 128];      // V' [hi|lo]

// ---------------------------------------------------------------------------
__device__ __forceinline__ uint32_t smem_u32(const void* p) {
    uint32_t a;
    asm("{ .reg .u64 t; cvta.to.shared.u64 t, %1; cvt.u32.u64 %0, t; }"
        : "=r"(a) : "l"(p));
    return a;
}
__device__ __forceinline__ uint32_t pk(__nv_bfloat16 a, __nv_bfloat16 b) {
    __nv_bfloat162 t = __halves2bfloat162(a, b);
    return *reinterpret_cast<uint32_t*>(&t);
}
__device__ __forceinline__ uint32_t pkf(float a, float b) {
    return pk(__float2bfloat16(a), __float2bfloat16(b));
}
__device__ __forceinline__ void ldsm4(uint32_t r[4], uint32_t addr) {
    asm volatile("ldmatrix.sync.aligned.m8n8.x4.shared.b16 {%0,%1,%2,%3}, [%4];"
                 : "=r"(r[0]), "=r"(r[1]), "=r"(r[2]), "=r"(r[3]) : "r"(addr));
}
__device__ __forceinline__ void ldsm4t(uint32_t r[4], uint32_t addr) {
    asm volatile("ldmatrix.sync.aligned.m8n8.x4.trans.shared.b16 {%0,%1,%2,%3}, [%4];"
                 : "=r"(r[0]), "=r"(r[1]), "=r"(r[2]), "=r"(r[3]) : "r"(addr));
}
__device__ __forceinline__ void mma16816(float c[4], const uint32_t a[4],
                                         uint32_t b0, uint32_t b1) {
    asm volatile("mma.sync.aligned.m16n8k16.row.col.f32.bf16.bf16.f32 "
                 "{%0,%1,%2,%3}, {%4,%5,%6,%7}, {%8,%9}, {%0,%1,%2,%3};"
                 : "+f"(c[0]), "+f"(c[1]), "+f"(c[2]), "+f"(c[3])
                 : "r"(a[0]), "r"(a[1]), "r"(a[2]), "r"(a[3]), "r"(b0), "r"(b1));
}
__device__ __forceinline__ void cpa16(uint32_t dst, const void* src) {
    asm volatile("cp.async.cg.shared.global [%0], [%1], 16;" :: "r"(dst), "l"(src));
}

// ---------------------------------------------------------------------------
// split3: fp32 [rows,K] -> bf16 [rows,3K]. loblk 1: [hi|lo|hi]; 2: [hi|hi|lo]
// ---------------------------------------------------------------------------
__global__ void split3_kernel(const float* __restrict__ src,
                              __nv_bfloat16* __restrict__ dst,
                              int rows, int K, int loblk) {
    int t = blockIdx.x * blockDim.x + threadIdx.x;
    int per4 = K >> 2;
    if (t >= rows * per4) return;
    int r = t / per4, c4 = (t - r * per4) * 4;
    float4 v = ((const float4*)src)[t];

    __nv_bfloat16 h0 = __float2bfloat16(v.x), h1 = __float2bfloat16(v.y);
    __nv_bfloat16 h2 = __float2bfloat16(v.z), h3 = __float2bfloat16(v.w);
    uint2 hp = make_uint2(pk(h0, h1), pk(h2, h3));
    uint2 lp = make_uint2(pkf(v.x - __bfloat162float(h0), v.y - __bfloat162float(h1)),
                          pkf(v.z - __bfloat162float(h2), v.w - __bfloat162float(h3)));

    __nv_bfloat16* d0 = dst + (size_t)r * (3 * K) + c4;
    *(uint2*)(d0)         = hp;
    *(uint2*)(d0 + K)     = (loblk == 1) ? lp : hp;
    *(uint2*)(d0 + 2 * K) = (loblk == 1) ? hp : lp;
}

// ---------------------------------------------------------------------------
// GEMM: C = A[M,K] @ B[N,K]^T. 128x128 tile, BK=64, 3-stage cp.async, 1 sync.
// mode 0: fp32 C.  mode 1: fused QKV split epilogue -> Qd/Kd/Vd.
// ---------------------------------------------------------------------------
#define BM 128
#define BN 128
#define BK 64
#define KSTRB 144                       // bytes per smem row (72 bf16, odd 16B)
#define STG_BYTES ((BM + BN) * KSTRB)   // 36864
#define GEMM_SMEM (3 * STG_BYTES)       // 110592

extern __shared__ char sh_raw[];

__global__ __launch_bounds__(256, 2)
void gemm_mma(const __nv_bfloat16* __restrict__ A,
              const __nv_bfloat16* __restrict__ B,
              float* __restrict__ C, int M, int N, int K, int mode,
              __nv_bfloat16* __restrict__ Qd,
              __nv_bfloat16* __restrict__ Kd,
              __nv_bfloat16* __restrict__ Vd) {
    const uint32_t sb = smem_u32(sh_raw);
    const int tid = threadIdx.x, wid = tid >> 5, lane = tid & 31;
    const int bm = blockIdx.y * BM, bn = blockIdx.x * BN;
    const int wm = (wid >> 2) * 64, wn = (wid & 3) * 32;
    const int g = lane >> 2, tg = lane & 3;
    const int lrow = lane & 15, lcol = (lane >> 4) * 8;

    auto load_stage = [&](int s, int kk) {
        uint32_t abase = sb + (uint32_t)s * STG_BYTES;
        uint32_t bbase = abase + BM * KSTRB;
#pragma unroll
        for (int i = 0; i < 8; ++i) {
            int c = tid + i * 256;
            if (c < 1024) {
                int row = c >> 3, k16 = c & 7;
                cpa16(abase + row * KSTRB + k16 * 16,
                      A + (size_t)(bm + row) * K + kk + k16 * 8);
            } else {
                int row = (c - 1024) >> 3, k16 = c & 7;
                cpa16(bbase + row * KSTRB + k16 * 16,
                      B + (size_t)(bn + row) * K + kk + k16 * 8);
            }
        }
        asm volatile("cp.async.commit_group;" ::: "memory");
    };

    float acc[4][4][4];
#pragma unroll
    for (int i = 0; i < 4; ++i)
#pragma unroll
        for (int j = 0; j < 4; ++j)
#pragma unroll
            for (int e = 0; e < 4; ++e) acc[i][j][e] = 0.0f;

    const int NC = K / BK;   // 48
    load_stage(0, 0);
    load_stage(1, BK);

    int st = 0;
    for (int c = 0; c < NC; ++c) {
        if (c + 1 < NC) asm volatile("cp.async.wait_group 1;" ::: "memory");
        else            asm volatile("cp.async.wait_group 0;" ::: "memory");
        __syncthreads();
        if (c + 2 < NC) {
            int ns = st + 2; if (ns >= 3) ns -= 3;
            load_stage(ns, (c + 2) * BK);
        }

        uint32_t abase = sb + (uint32_t)st * STG_BYTES;
        uint32_t bbase = abase + BM * KSTRB;
#pragma unroll
        for (int ks = 0; ks < 4; ++ks) {
            uint32_t a[4][4];
#pragma unroll
            for (int mt = 0; mt < 4; ++mt)
                ldsm4(a[mt], abase + (wm + mt * 16 + lrow) * KSTRB + (ks * 16 + lcol) * 2);
            uint32_t bf[4][2];
#pragma unroll
            for (int nb = 0; nb < 2; ++nb) {
                uint32_t r[4];
                ldsm4(r, bbase + (wn + nb * 16 + lrow) * KSTRB + (ks * 16 + lcol) * 2);
                bf[nb * 2][0] = r[0];     bf[nb * 2][1] = r[2];
                bf[nb * 2 + 1][0] = r[1]; bf[nb * 2 + 1][1] = r[3];
            }
#pragma unroll
            for (int mt = 0; mt < 4; ++mt)
#pragma unroll
                for (int nt = 0; nt < 4; ++nt)
                    mma16816(acc[mt][nt], a[mt], bf[nt][0], bf[nt][1]);
        }
        ++st; if (st >= 3) st = 0;
    }

    if (mode == 0) {
#pragma unroll
        for (int mt = 0; mt < 4; ++mt) {
            int r0 = bm + wm + mt * 16 + g;
#pragma unroll
            for (int nt = 0; nt < 4; ++nt) {
                int col = bn + wn + nt * 8 + tg * 2;
                *(float2*)(C + (size_t)r0 * N + col) =
                    make_float2(acc[mt][nt][0], acc[mt][nt][1]);
                *(float2*)(C + (size_t)(r0 + 8) * N + col) =
                    make_float2(acc[mt][nt][2], acc[mt][nt][3]);
            }
        }
    } else {
        // fused QKV split epilogue
#pragma unroll
        for (int nt = 0; nt < 4; ++nt) {
            int cbase = bn + wn + nt * 8 + tg * 2;
            int plane = cbase >> 10, rem = cbase & 1023;
            int h = rem >> 6, d = rem & 63;
#pragma unroll
            for (int mt = 0; mt < 4; ++mt) {
#pragma unroll
                for (int rr = 0; rr < 2; ++rr) {
                    int row = bm + wm + mt * 16 + g + rr * 8;
                    int b = row >> 11, s = row & 2047;
                    float v0 = acc[mt][nt][rr * 2], v1 = acc[mt][nt][rr * 2 + 1];
                    __nv_bfloat16 h0 = __float2bfloat16(v0), h1 = __float2bfloat16(v1);
                    uint32_t hi = pk(h0, h1);
                    uint32_t lo = pkf(v0 - __bfloat162float(h0), v1 - __bfloat162float(h1));
                    size_t bh = (size_t)(b * 16 + h);
                    if (plane == 0) {
                        __nv_bfloat16* p = Qd + (bh * 2048 + s) * 192 + d;
                        *(uint32_t*)(p)       = hi;
                        *(uint32_t*)(p + 64)  = lo;
                        *(uint32_t*)(p + 128) = hi;
                    } else if (plane == 1) {
                        __nv_bfloat16* p = Kd + (bh * 2048 + s) * 192 + d;
                        *(uint32_t*)(p)       = hi;
                        *(uint32_t*)(p + 64)  = hi;
                        *(uint32_t*)(p + 128) = lo;
                    } else {
                        __nv_bfloat16* p = Vd + (bh * 2048 + s) * 128 + d;
                        *(uint32_t*)(p)      = hi;
                        *(uint32_t*)(p + 64) = lo;
                    }
                }
            }
        }
    }
}

// ---------------------------------------------------------------------------
// Flash attention v2: BR=128, BC=64, 256 threads (8 warps x 16 rows), causal.
// Inputs preconverted bf16. Writes E' split [hi|lo|hi] to g_a2.
// ---------------------------------------------------------------------------
#define QSTR 200   // smem stride (el) for Q'/K' (192 cols)
#define VSTR 136   // for V (128 cols)
#define ATT_SMEM ((128 * QSTR + 64 * QSTR + 64 * VSTR) * 2)   // 94208

__global__ __launch_bounds__(256, 2)
void attn_mma2(const __nv_bfloat16* __restrict__ Qg,
               const __nv_bfloat16* __restrict__ Kg,
               const __nv_bfloat16* __restrict__ Vg,
               __nv_bfloat16* __restrict__ Eo) {
    const uint32_t sbQ = smem_u32(sh_raw);
    const uint32_t sbK = sbQ + 128 * QSTR * 2;
    const uint32_t sbV = sbK + 64 * QSTR * 2;

    const int tid = threadIdx.x, wid = tid >> 5, lane = tid & 31;
    const int qi = (gridDim.x - 1) - blockIdx.x;     // big tiles first
    const int q0 = qi * 128;
    const int h = blockIdx.y, b = blockIdx.z;
    const size_t bh = (size_t)(b * 16 + h);
    const int g = lane >> 2, tg = lane & 3;
    const int lrow = lane & 15, lcol = (lane >> 4) * 8;

    // load Q' tile (128 x 192)
    {
        const __nv_bfloat16* qg = Qg + (bh * 2048 + q0) * 192;
#pragma unroll
        for (int i = 0; i < 12; ++i) {
            int c = tid + i * 256;
            int row = c / 24, c16 = c % 24;
            cpa16(sbQ + (row * QSTR + c16 * 8) * 2, qg + row * 192 + c16 * 8);
        }
        asm volatile("cp.async.commit_group;" ::: "memory");
    }

    float m0 = -1e30f, m1 = -1e30f, l0 = 0.0f, l1 = 0.0f;
    float o[8][4];
#pragma unroll
    for (int i = 0; i < 8; ++i)
#pragma unroll
        for (int j = 0; j < 4; ++j) o[i][j] = 0.0f;

    const int ntiles = 2 * qi + 2;
    const int rowg0 = q0 + wid * 16 + g, rowg1 = rowg0 + 8;

    for (int t = 0; t < ntiles; ++t) {
        const int k0 = t * 64;
        __syncthreads();   // previous K/V consumed

        const __nv_bfloat16* kg = Kg + (bh * 2048 + k0) * 192;
#pragma unroll
        for (int i = 0; i < 6; ++i) {
            int c = tid + i * 256;
            int row = c / 24, c16 = c % 24;
            cpa16(sbK + (row * QSTR + c16 * 8) * 2, kg + row * 192 + c16 * 8);
        }
        const __nv_bfloat16* vg = Vg + (bh * 2048 + k0) * 128;
#pragma unroll
        for (int i = 0; i < 4; ++i) {
            int c = tid + i * 256;
            int row = c >> 4, c16 = c & 15;
            cpa16(sbV + (row * VSTR + c16 * 8) * 2, vg + row * 128 + c16 * 8);
        }
        asm volatile("cp.async.commit_group;" ::: "memory");
        asm volatile("cp.async.wait_group 0;" ::: "memory");
        __syncthreads();

        // ---- S = Q' K'^T (K'=192)
        float s[8][4];
#pragma unroll
        for (int i = 0; i < 8; ++i)
#pragma unroll
            for (int j = 0; j < 4; ++j) s[i][j] = 0.0f;

#pragma unroll
        for (int ks = 0; ks < 12; ++ks) {
            uint32_t qa[4];
            ldsm4(qa, sbQ + ((wid * 16 + lrow) * QSTR + ks * 16 + lcol) * 2);
#pragma unroll
            for (int nb = 0; nb < 4; ++nb) {
                uint32_t r[4];
                ldsm4(r, sbK + ((nb * 16 + lrow) * QSTR + ks * 16 + lcol) * 2);
                mma16816(s[nb * 2],     qa, r[0], r[2]);
                mma16816(s[nb * 2 + 1], qa, r[1], r[3]);
            }
        }

        // ---- scale + causal mask (only last two tiles can touch diagonal)
        const bool diag = (t >= ntiles - 2);
#pragma unroll
        for (int nt = 0; nt < 8; ++nt)
#pragma unroll
            for (int ee = 0; ee < 4; ++ee) {
                int col = k0 + nt * 8 + tg * 2 + (ee & 1);
                int row = (ee < 2) ? rowg0 : rowg1;
                if (diag && col > row) s[nt][ee] = -1e30f;
                else                   s[nt][ee] *= 0.125f;
            }

        // ---- online softmax (quad reductions)
        float rmax0 = -1e30f, rmax1 = -1e30f;
#pragma unroll
        for (int nt = 0; nt < 8; ++nt) {
            rmax0 = fmaxf(rmax0, fmaxf(s[nt][0], s[nt][1]));
            rmax1 = fmaxf(rmax1, fmaxf(s[nt][2], s[nt][3]));
        }
        rmax0 = fmaxf(rmax0, __shfl_xor_sync(0xffffffffu, rmax0, 1));
        rmax0 = fmaxf(rmax0, __shfl_xor_sync(0xffffffffu, rmax0, 2));
        rmax1 = fmaxf(rmax1, __shfl_xor_sync(0xffffffffu, rmax1, 1));
        rmax1 = fmaxf(rmax1, __shfl_xor_sync(0xffffffffu, rmax1, 2));

        float mn0 = fmaxf(m0, rmax0), mn1 = fmaxf(m1, rmax1);
        float al0 = __expf(m0 - mn0), al1 = __expf(m1 - mn1);
        m0 = mn0; m1 = mn1;

        float rs0 = 0.0f, rs1 = 0.0f;
#pragma unroll
        for (int nt = 0; nt < 8; ++nt) {
            s[nt][0] = __expf(s[nt][0] - m0);
            s[nt][1] = __expf(s[nt][1] - m0);
            s[nt][2] = __expf(s[nt][2] - m1);
            s[nt][3] = __expf(s[nt][3] - m1);
            rs0 += s[nt][0] + s[nt][1];
            rs1 += s[nt][2] + s[nt][3];
        }
        rs0 += __shfl_xor_sync(0xffffffffu, rs0, 1);
        rs0 += __shfl_xor_sync(0xffffffffu, rs0, 2);
        rs1 += __shfl_xor_sync(0xffffffffu, rs1, 1);
        rs1 += __shfl_xor_sync(0xffffffffu, rs1, 2);
        l0 = l0 * al0 + rs0;
        l1 = l1 * al1 + rs1;
#pragma unroll
        for (int nt = 0; nt < 8; ++nt) {
            o[nt][0] *= al0; o[nt][1] *= al0;
            o[nt][2] *= al1; o[nt][3] *= al1;
        }

        // ---- P -> bf16 hi/lo A-fragments, straight from S fragments
        uint32_t ph[4][4], pl[4][4];
#pragma unroll
        for (int kc = 0; kc < 4; ++kc) {
            const float* se = s[kc * 2];
            const float* so = s[kc * 2 + 1];
            __nv_bfloat16 he0 = __float2bfloat16(se[0]), he1 = __float2bfloat16(se[1]);
            __nv_bfloat16 he2 = __float2bfloat16(se[2]), he3 = __float2bfloat16(se[3]);
            __nv_bfloat16 ho0 = __float2bfloat16(so[0]), ho1 = __float2bfloat16(so[1]);
            __nv_bfloat16 ho2 = __float2bfloat16(so[2]), ho3 = __float2bfloat16(so[3]);
            ph[kc][0] = pk(he0, he1); ph[kc][1] = pk(he2, he3);
            ph[kc][2] = pk(ho0, ho1); ph[kc][3] = pk(ho2, ho3);
            pl[kc][0] = pkf(se[0] - __bfloat162float(he0), se[1] - __bfloat162float(he1));
            pl[kc][1] = pkf(se[2] - __bfloat162float(he2), se[3] - __bfloat162float(he3));
            pl[kc][2] = pkf(so[0] - __bfloat162float(ho0), so[1] - __bfloat162float(ho1));
            pl[kc][3] = pkf(so[2] - __bfloat162float(ho2), so[3] - __bfloat162float(ho3));
        }

        // ---- O += Ph*Vh + Pl*Vh + Ph*Vl   (V via ldmatrix.trans, row-major [c,d])
#pragma unroll
        for (int kc = 0; kc < 4; ++kc) {
#pragma unroll
            for (int db = 0; db < 4; ++db) {
                uint32_t rh[4];
                ldsm4t(rh, sbV + ((kc * 16 + lrow) * VSTR + db * 16 + lcol) * 2);
                mma16816(o[db * 2],     ph[kc], rh[0], rh[1]);
                mma16816(o[db * 2 + 1], ph[kc], rh[2], rh[3]);
                mma16816(o[db * 2],     pl[kc], rh[0], rh[1]);
                mma16816(o[db * 2 + 1], pl[kc], rh[2], rh[3]);
                uint32_t rl[4];
                ldsm4t(rl, sbV + ((kc * 16 + lrow) * VSTR + 64 + db * 16 + lcol) * 2);
                mma16816(o[db * 2],     ph[kc], rl[0], rl[1]);
                mma16816(o[db * 2 + 1], ph[kc], rl[2], rl[3]);
            }
        }
    }

    // ---- epilogue: write E' split [hi|lo|hi] to Eo [4096, 3072]
    float inv0 = 1.0f / l0, inv1 = 1.0f / l1;
    size_t r0 = (size_t)(b * 2048) + rowg0;
    size_t r1 = (size_t)(b * 2048) + rowg1;
#pragma unroll
    for (int nt = 0; nt < 8; ++nt) {
        int col = h * 64 + nt * 8 + tg * 2;
        float a0 = o[nt][0] * inv0, a1 = o[nt][1] * inv0;
        float b0 = o[nt][2] * inv1, b1 = o[nt][3] * inv1;
        __nv_bfloat16 ah0 = __float2bfloat16(a0), ah1 = __float2bfloat16(a1);
        __nv_bfloat16 bh0 = __float2bfloat16(b0), bh1 = __float2bfloat16(b1);
        uint32_t ahi = pk(ah0, ah1);
        uint32_t alo = pkf(a0 - __bfloat162float(ah0), a1 - __bfloat162float(ah1));
        uint32_t bhi = pk(bh0, bh1);
        uint32_t blo = pkf(b0 - __bfloat162float(bh0), b1 - __bfloat162float(bh1));
        __nv_bfloat16* p0 = Eo + r0 * K3 + col;
        __nv_bfloat16* p1 = Eo + r1 * K3 + col;
        *(uint32_t*)(p0)        = ahi;
        *(uint32_t*)(p0 + 1024) = alo;
        *(uint32_t*)(p0 + 2048) = ahi;
        *(uint32_t*)(p1)        = bhi;
        *(uint32_t*)(p1 + 1024) = blo;
        *(uint32_t*)(p1 + 2048) = bhi;
    }
}

// ---------------------------------------------------------------------------
// launch
// ---------------------------------------------------------------------------
extern "C" void kernel_launch(void* const* d_in, const int* in_sizes, int n_in,
                              void* d_out, int out_size) {
    (void)in_sizes; (void)n_in; (void)out_size;
    const float* x    = (const float*)d_in[0];
    const float* wqkv = (const float*)d_in[1];
    const float* w0   = (const float*)d_in[2];
    float* out = (float*)d_out;

    __nv_bfloat16 *a2, *w2, *qd, *kd, *vd;
    cudaGetSymbolAddress((void**)&a2, g_a2);
    cudaGetSymbolAddress((void**)&w2, g_w2);
    cudaGetSymbolAddress((void**)&qd, g_q);
    cudaGetSymbolAddress((void**)&kd, g_k);
    cudaGetSymbolAddress((void**)&vd, g_v);

    cudaFuncSetAttribute(gemm_mma,
                         cudaFuncAttributeMaxDynamicSharedMemorySize, GEMM_SMEM);
    cudaFuncSetAttribute(attn_mma2,
                         cudaFuncAttributeMaxDynamicSharedMemorySize, ATT_SMEM);

    const int M = 4096;

    split3_kernel<<<(M * E_DIM / 4 + 255) / 256, 256>>>(x, a2, M, E_DIM, 1);
    split3_kernel<<<(3 * E_DIM * E_DIM / 4 + 255) / 256, 256>>>(wqkv, w2, 3 * E_DIM, E_DIM, 2);

    // gemm1: QKV, fused split epilogue -> Q'/K'/V'
    gemm_mma<<<dim3(3 * E_DIM / BN, M / BM), 256, GEMM_SMEM>>>(
        a2, w2, nullptr, M, 3 * E_DIM, K3, 1, qd, kd, vd);

    // attention -> E' (into g_a2)
    attn_mma2<<<dim3(S_LEN / 128, 16, 2), 256, ATT_SMEM>>>(qd, kd, vd, a2);

    split3_kernel<<<(E_DIM * E_DIM / 4 + 255) / 256, 256>>>(w0, w2, E_DIM, E_DIM, 2);

    // gemm2: out projection, fp32 epilogue
    gemm_mma<<<dim3(E_DIM / BN, M / BM), 256, GEMM_SMEM>>>(
        a2, w2, out, M, E_DIM, K3, 0, nullptr, nullptr, nullptr);
}